// round 13
// baseline (speedup 1.0000x reference)
#include <cuda_runtime.h>
#include <cuda_fp16.h>
#include <cstdint>

#define NCH   8
#define HDIM  512
#define TTOK  32768
#define KTOT  4096
#define BM    64
#define BN    256
#define BK    32
#define NSTG  (KTOT/BK)      /* 128 */
#define NBUF  4
#define EPS_F 1e-5f

/* GEMM smem layout (bytes): padded 80B rows, 4-stage ring */
#define A_ST  (64*80)             /* 5120 */
#define SB2   (NBUF*A_ST)         /* 20480 */
#define B_ST  (256*80)            /* 20480 */
#define SMEM_TOTAL (SB2 + NBUF*B_ST) /* 102400 */

__device__ float  g_wg[NCH*HDIM];
__device__ float  g_bg[NCH*HDIM];
__device__ float  g_q[NCH*4];
__device__ __half g_Bh[HDIM*KTOT];
__device__ __half g_Ah[(size_t)TTOK*KTOT];

__device__ __forceinline__ uint32_t smem_u32(const void* p) {
    uint32_t a;
    asm("{ .reg .u64 t; cvta.to.shared.u64 t, %1; cvt.u32.u64 %0, t; }" : "=r"(a) : "l"(p));
    return a;
}
__device__ __forceinline__ float geluf(float v) {          /* exact: final output only */
    return 0.5f * v * (1.0f + erff(v * 0.7071067811865476f));
}
__device__ __forceinline__ float gelu_fast(float v) {
    float t = v * v;
    float y = v * fmaf(t, 0.0356774081f, 0.7978845608f);
    float e = __expf(-2.0f * y);
    return __fdividef(v, 1.0f + e);
}
__device__ __forceinline__ uint32_t packh2(float a, float b) {
    __half2 h = __floats2half2_rn(a, b);
    return *reinterpret_cast<uint32_t*>(&h);
}

#define LDSM4(d0, d1, d2, d3, addr)                                           \
    asm volatile("ldmatrix.sync.aligned.m8n8.x4.shared.b16 {%0,%1,%2,%3}, [%4];" \
                 : "=r"(d0), "=r"(d1), "=r"(d2), "=r"(d3) : "r"(addr))
#define MMA16816(c, a, b)                                                     \
    asm volatile("mma.sync.aligned.m16n8k16.row.col.f32.f16.f16.f32 "         \
                 "{%0,%1,%2,%3}, {%4,%5,%6,%7}, {%8,%9}, {%0,%1,%2,%3};"      \
                 : "+f"((c)[0]), "+f"((c)[1]), "+f"((c)[2]), "+f"((c)[3])     \
                 : "r"((a)[0]), "r"((a)[1]), "r"((a)[2]), "r"((a)[3]),        \
                   "r"((b)[0]), "r"((b)[1]))

/* ---- prep 1: per-channel LN closed-form tables ---- */
__device__ __forceinline__ float bsum512(float v, float* red) {
    #pragma unroll
    for (int o = 16; o > 0; o >>= 1) v += __shfl_xor_sync(0xffffffffu, v, o);
    __syncthreads();
    if ((threadIdx.x & 31) == 0) red[threadIdx.x >> 5] = v;
    __syncthreads();
    float s = 0.f;
    #pragma unroll
    for (int i = 0; i < 16; i++) s += red[i];
    return s;
}
__global__ void __launch_bounds__(512) prep_channel_kernel(
    const float* __restrict__ enc_w, const float* __restrict__ enc_b,
    const float* __restrict__ enc_gamma)
{
    __shared__ float red[16];
    int c = blockIdx.x, t = threadIdx.x;
    float w = enc_w[c*HDIM+t], b = enc_b[c*HDIM+t];
    float wm = bsum512(w, red) * (1.0f/HDIM);
    float bm = bsum512(b, red) * (1.0f/HDIM);
    float wp = w - wm, bp = b - bm;
    float sww = bsum512(wp*wp, red);
    float swb = bsum512(wp*bp, red);
    float sbb = bsum512(bp*bp, red);
    float ga = enc_gamma[c*HDIM+t];
    g_wg[c*HDIM+t] = wp * ga;
    g_bg[c*HDIM+t] = bp * ga;
    if (t == 0) {
        g_q[c*4+0] = sww * (1.0f/HDIM);
        g_q[c*4+1] = 2.0f * swb * (1.0f/HDIM);
        g_q[c*4+2] = sbb * (1.0f/HDIM);
    }
}

/* ---- prep 2: mod_w fp32 -> fp16 ---- */
__global__ void __launch_bounds__(256) prep_b_kernel(const float* __restrict__ mod_w) {
    int i = blockIdx.x * 256 + threadIdx.x;
    float4 v = __ldg(((const float4*)mod_w) + i);
    uint2 o;
    o.x = packh2(v.x, v.y);
    o.y = packh2(v.z, v.w);
    ((uint2*)g_Bh)[i] = o;
}

/* ---- gen A: thread owns fixed 16-wide k-slice, 32 rows/block ---- */
__global__ void __launch_bounds__(256) gen_a_kernel(
    const float* __restrict__ x, const float* __restrict__ enc_beta)
{
    int tid = threadIdx.x;
    int k0 = tid * 16;
    int c  = tid >> 5;

    float4 w0 = *(const float4*)&g_wg[k0],   w1 = *(const float4*)&g_wg[k0+4];
    float4 w2 = *(const float4*)&g_wg[k0+8], w3 = *(const float4*)&g_wg[k0+12];
    float4 b0 = *(const float4*)&g_bg[k0],   b1 = *(const float4*)&g_bg[k0+4];
    float4 b2 = *(const float4*)&g_bg[k0+8], b3 = *(const float4*)&g_bg[k0+12];
    float4 t0 = __ldg((const float4*)&enc_beta[k0]);
    float4 t1 = __ldg((const float4*)&enc_beta[k0+4]);
    float4 t2 = __ldg((const float4*)&enc_beta[k0+8]);
    float4 t3 = __ldg((const float4*)&enc_beta[k0+12]);
    float qa = g_q[c*4+0], qb = g_q[c*4+1], qc = g_q[c*4+2];

    int row0 = blockIdx.x * 32;
    for (int ri = 0; ri < 32; ri++) {
        int token = row0 + ri;
        float xv = __ldg(&x[c*TTOK + token]);
        float rr = rsqrtf(fmaf(xv, fmaf(xv, qa, qb), qc) + EPS_F);
        uint4 o0, o1;
        #define G(W,B,T) gelu_fast(fmaf(fmaf(xv,(W),(B)), rr, (T)))
        o0.x = packh2(G(w0.x,b0.x,t0.x), G(w0.y,b0.y,t0.y));
        o0.y = packh2(G(w0.z,b0.z,t0.z), G(w0.w,b0.w,t0.w));
        o0.z = packh2(G(w1.x,b1.x,t1.x), G(w1.y,b1.y,t1.y));
        o0.w = packh2(G(w1.z,b1.z,t1.z), G(w1.w,b1.w,t1.w));
        o1.x = packh2(G(w2.x,b2.x,t2.x), G(w2.y,b2.y,t2.y));
        o1.y = packh2(G(w2.z,b2.z,t2.z), G(w2.w,b2.w,t2.w));
        o1.z = packh2(G(w3.x,b3.x,t3.x), G(w3.y,b3.y,t3.y));
        o1.w = packh2(G(w3.z,b3.z,t3.z), G(w3.w,b3.w,t3.w));
        #undef G
        uint4* dst = (uint4*)(g_Ah + (size_t)token*KTOT + k0);
        dst[0] = o0;
        dst[1] = o1;
    }
}

/* ---- fp16 mma.sync GEMM: frag double-buffer + sync hidden under MMA ---- */
__global__ void __launch_bounds__(256, 2) gemm_kernel(float* __restrict__ out)
{
    extern __shared__ char smem[];
    uint32_t sb = smem_u32(smem);
    int tid = threadIdx.x;
    int mt = blockIdx.x >> 1, nt = blockIdx.x & 1;

    int wid = tid >> 5, lane = tid & 31;
    int wr = wid >> 2, wc = wid & 3;
    uint32_t aAddr = (uint32_t)((wr*32 + (lane & 15)) * 80 + (lane >> 4) * 16);
    uint32_t bAddr = (uint32_t)((wc*64 + ((lane >> 4) & 1)*8 + (lane & 7)) * 80
                                + ((lane >> 3) & 1) * 16);

    float acc[2][8][4];
    #pragma unroll
    for (int mi = 0; mi < 2; mi++)
        #pragma unroll
        for (int ni = 0; ni < 8; ni++)
            #pragma unroll
            for (int e = 0; e < 4; e++) acc[mi][ni][e] = 0.f;

    uint32_t af[2][2][4];   /* [phase][mi][reg] */
    uint32_t bf[2][8][2];   /* [phase][ni][reg] */

    const __half* Abase = g_Ah + (size_t)(mt*BM)*KTOT;
    const __half* Bbase = g_Bh + (size_t)(nt*BN)*KTOT;

#define CP_STAGE(sidx, buf)                                                   \
    {                                                                         \
        {                                                                     \
            int rw = tid >> 2, ch = tid & 3;                                  \
            uint32_t dst = sb + (buf)*A_ST + (uint32_t)(rw*80 + ch*16);       \
            const __half* src = Abase + (size_t)rw*KTOT + (sidx)*32 + ch*8;   \
            asm volatile("cp.async.cg.shared.global [%0], [%1], 16;"          \
                         :: "r"(dst), "l"(src) : "memory");                   \
        }                                                                     \
        _Pragma("unroll")                                                     \
        for (int i2 = 0; i2 < 4; i2++) {                                      \
            int lin = tid + 256*i2;                                           \
            int rw = lin >> 2, ch = lin & 3;                                  \
            uint32_t dst = sb + SB2 + (buf)*B_ST + (uint32_t)(rw*80 + ch*16); \
            const __half* src = Bbase + (size_t)rw*KTOT + (sidx)*32 + ch*8;   \
            asm volatile("cp.async.cg.shared.global [%0], [%1], 16;"          \
                         :: "r"(dst), "l"(src) : "memory");                   \
        }                                                                     \
        asm volatile("cp.async.commit_group;" ::: "memory");                  \
    }

#define LOAD_FRAGS(buf, kh, ph)                                               \
    {                                                                         \
        uint32_t abuf = sb + (buf)*A_ST + aAddr + (uint32_t)((kh)*32);        \
        uint32_t bbuf = sb + SB2 + (buf)*B_ST + bAddr + (uint32_t)((kh)*32);  \
        _Pragma("unroll")                                                     \
        for (int mi = 0; mi < 2; mi++)                                        \
            LDSM4(af[ph][mi][0], af[ph][mi][1], af[ph][mi][2], af[ph][mi][3], \
                  abuf + (uint32_t)(mi*1280));                                \
        _Pragma("unroll")                                                     \
        for (int p = 0; p < 4; p++)                                           \
            LDSM4(bf[ph][2*p][0], bf[ph][2*p][1],                             \
                  bf[ph][2*p+1][0], bf[ph][2*p+1][1],                         \
                  bbuf + (uint32_t)(p*1280));                                 \
    }

#define MMA_BLOCK(ph)                                                         \
    {                                                                         \
        _Pragma("unroll")                                                     \
        for (int mi = 0; mi < 2; mi++)                                        \
            _Pragma("unroll")                                                 \
            for (int ni = 0; ni < 8; ni++)                                    \
                MMA16816(acc[mi][ni], af[ph][mi], bf[ph][ni]);                \
    }

    /* stage body: fb = s&3 (current), nb = (s+1)&3 (next), pb = (s+3)&3 =
       (s-1)&3 (prefetch target, fully consumed in iteration s-1).  All
       compile-time via the 4x-unrolled loop below. */
#define STAGE_BODY(s, fb, nb, pb)                                             \
    {                                                                         \
        MMA_BLOCK(0);                               /* covers wait+barrier */ \
        asm volatile("cp.async.wait_group 1;" ::: "memory");                  \
        __syncthreads();                                                      \
        if ((s) + 3 < NSTG) CP_STAGE((s) + 3, (pb));                          \
        LOAD_FRAGS((fb), 1, 1);                                               \
        if ((s) + 1 < NSTG) LOAD_FRAGS((nb), 0, 0);                           \
        MMA_BLOCK(1);                                                         \
    }

    /* prologue: fill 3 ring slots, land stage 0 frags */
    CP_STAGE(0, 0);
    CP_STAGE(1, 1);
    CP_STAGE(2, 2);
    asm volatile("cp.async.wait_group 2;" ::: "memory");
    __syncthreads();
    LOAD_FRAGS(0, 0, 0);

    for (int s4 = 0; s4 < NSTG; s4 += 4) {
        { int s = s4 + 0; STAGE_BODY(s, 0, 1, 3); }
        { int s = s4 + 1; STAGE_BODY(s, 1, 2, 0); }
        { int s = s4 + 2; STAGE_BODY(s, 2, 3, 1); }
        { int s = s4 + 3; STAGE_BODY(s, 3, 0, 2); }
    }

    /* epilogue: raw y (pre-bias) to gmem */
    int gr = mt*BM + wr*32;
    int gc = nt*BN + wc*64;
    #pragma unroll
    for (int mi = 0; mi < 2; mi++) {
        int row0 = gr + mi*16 + (lane >> 2);
        #pragma unroll
        for (int ni = 0; ni < 8; ni++) {
            int col = gc + ni*8 + ((lane & 3) << 1);
            *(float2*)&out[(size_t)row0*HDIM + col] =
                make_float2(acc[mi][ni][0], acc[mi][ni][1]);
            *(float2*)&out[(size_t)(row0+8)*HDIM + col] =
                make_float2(acc[mi][ni][2], acc[mi][ni][3]);
        }
    }
}

/* ---- bias + LayerNorm + GELU (exact erff), row-per-block ---- */
__global__ void __launch_bounds__(128) ln_gelu_kernel(
    float* __restrict__ y, const float* __restrict__ mod_b,
    const float* __restrict__ mg, const float* __restrict__ mb)
{
    __shared__ float red[8];
    int t = threadIdx.x, lane = t & 31, w = t >> 5;
    size_t base = (size_t)blockIdx.x * HDIM;
    float4 v = *(float4*)&y[base + t*4];
    float4 b = __ldg((const float4*)&mod_b[t*4]);
    v.x += b.x; v.y += b.y; v.z += b.z; v.w += b.w;
    float s = v.x + v.y + v.z + v.w;
    float q = v.x*v.x + v.y*v.y + v.z*v.z + v.w*v.w;
    #pragma unroll
    for (int o = 16; o > 0; o >>= 1) {
        s += __shfl_xor_sync(0xffffffffu, s, o);
        q += __shfl_xor_sync(0xffffffffu, q, o);
    }
    if (lane == 0) { red[w] = s; red[4+w] = q; }
    __syncthreads();
    float S = red[0]+red[1]+red[2]+red[3];
    float Q = red[4]+red[5]+red[6]+red[7];
    float mu = S * (1.0f/HDIM);
    float var = Q * (1.0f/HDIM) - mu*mu;
    float rrv = rsqrtf(var + EPS_F);
    float4 g = __ldg((const float4*)&mg[t*4]);
    float4 be = __ldg((const float4*)&mb[t*4]);
    float4 o;
    o.x = geluf(fmaf((v.x-mu)*rrv, g.x, be.x));
    o.y = geluf(fmaf((v.y-mu)*rrv, g.y, be.y));
    o.z = geluf(fmaf((v.z-mu)*rrv, g.z, be.z));
    o.w = geluf(fmaf((v.w-mu)*rrv, g.w, be.w));
    *(float4*)&y[base + t*4] = o;
}

extern "C" void kernel_launch(void* const* d_in, const int* in_sizes, int n_in,
                              void* d_out, int out_size) {
    const float* x         = (const float*)d_in[0];
    const float* enc_w     = (const float*)d_in[1];
    const float* enc_b     = (const float*)d_in[2];
    const float* enc_gamma = (const float*)d_in[3];
    const float* enc_beta  = (const float*)d_in[4];
    const float* mod_w     = (const float*)d_in[5];
    const float* mod_b     = (const float*)d_in[6];
    const float* mod_gamma = (const float*)d_in[7];
    const float* mod_beta  = (const float*)d_in[8];
    float* out = (float*)d_out;

    cudaFuncSetAttribute(gemm_kernel,
                         cudaFuncAttributeMaxDynamicSharedMemorySize, SMEM_TOTAL);

    prep_channel_kernel<<<NCH, 512>>>(enc_w, enc_b, enc_gamma);
    prep_b_kernel<<<(HDIM*KTOT/4)/256, 256>>>(mod_w);
    gen_a_kernel<<<TTOK/32, 256>>>(x, enc_beta);
    gemm_kernel<<<(TTOK/BM)*2, 256, SMEM_TOTAL>>>(out);
    ln_gelu_kernel<<<TTOK, 128>>>(out, mod_b, mod_gamma, mod_beta);
}

// round 14
// speedup vs baseline: 1.8253x; 1.8253x over previous
#include <cuda_runtime.h>
#include <cuda_fp16.h>
#include <cstdint>

#define NCH   8
#define HDIM  512
#define TTOK  32768
#define KTOT  4096
#define BM    64
#define BK    32
#define NSTG  (KTOT/BK)      /* 128 */
#define NBUF  4
#define EPS_F 1e-5f

/* per-group stage slab: A 64x64B (4096) + B 128x64B (8192) = 12288; 4-ring x 2 groups */
#define SLAB     12288
#define A_BYTES  4096
#define GRP      (NBUF*SLAB)          /* 49152 */
#define SMEM_TOTAL (2*GRP)            /* 98304 */

__device__ float  g_wg[NCH*HDIM];
__device__ float  g_bg[NCH*HDIM];
__device__ float  g_q[NCH*4];
__device__ __half g_Bh[HDIM*KTOT];
__device__ __half g_Ah[(size_t)TTOK*KTOT];

__device__ __forceinline__ uint32_t smem_u32(const void* p) {
    uint32_t a;
    asm("{ .reg .u64 t; cvta.to.shared.u64 t, %1; cvt.u32.u64 %0, t; }" : "=r"(a) : "l"(p));
    return a;
}
__device__ __forceinline__ float geluf(float v) {
    return 0.5f * v * (1.0f + erff(v * 0.7071067811865476f));
}
__device__ __forceinline__ float gelu_fast(float v) {
    float t = v * v;
    float y = v * fmaf(t, 0.0356774081f, 0.7978845608f);
    float e = __expf(-2.0f * y);
    return __fdividef(v, 1.0f + e);
}
__device__ __forceinline__ uint32_t packh2(float a, float b) {
    __half2 h = __floats2half2_rn(a, b);
    return *reinterpret_cast<uint32_t*>(&h);
}

#define LDSM4(d0, d1, d2, d3, addr)                                           \
    asm volatile("ldmatrix.sync.aligned.m8n8.x4.shared.b16 {%0,%1,%2,%3}, [%4];" \
                 : "=r"(d0), "=r"(d1), "=r"(d2), "=r"(d3) : "r"(addr))
#define MMA16816(c, a, b)                                                     \
    asm volatile("mma.sync.aligned.m16n8k16.row.col.f32.f16.f16.f32 "         \
                 "{%0,%1,%2,%3}, {%4,%5,%6,%7}, {%8,%9}, {%0,%1,%2,%3};"      \
                 : "+f"((c)[0]), "+f"((c)[1]), "+f"((c)[2]), "+f"((c)[3])     \
                 : "r"((a)[0]), "r"((a)[1]), "r"((a)[2]), "r"((a)[3]),        \
                   "r"((b)[0]), "r"((b)[1]))

/* ---- prep 1: per-channel LN closed-form tables ---- */
__device__ __forceinline__ float bsum512(float v, float* red) {
    #pragma unroll
    for (int o = 16; o > 0; o >>= 1) v += __shfl_xor_sync(0xffffffffu, v, o);
    __syncthreads();
    if ((threadIdx.x & 31) == 0) red[threadIdx.x >> 5] = v;
    __syncthreads();
    float s = 0.f;
    #pragma unroll
    for (int i = 0; i < 16; i++) s += red[i];
    return s;
}
__global__ void __launch_bounds__(512) prep_channel_kernel(
    const float* __restrict__ enc_w, const float* __restrict__ enc_b,
    const float* __restrict__ enc_gamma)
{
    __shared__ float red[16];
    int c = blockIdx.x, t = threadIdx.x;
    float w = enc_w[c*HDIM+t], b = enc_b[c*HDIM+t];
    float wm = bsum512(w, red) * (1.0f/HDIM);
    float bm = bsum512(b, red) * (1.0f/HDIM);
    float wp = w - wm, bp = b - bm;
    float sww = bsum512(wp*wp, red);
    float swb = bsum512(wp*bp, red);
    float sbb = bsum512(bp*bp, red);
    float ga = enc_gamma[c*HDIM+t];
    g_wg[c*HDIM+t] = wp * ga;
    g_bg[c*HDIM+t] = bp * ga;
    if (t == 0) {
        g_q[c*4+0] = sww * (1.0f/HDIM);
        g_q[c*4+1] = 2.0f * swb * (1.0f/HDIM);
        g_q[c*4+2] = sbb * (1.0f/HDIM);
    }
}

/* ---- prep 2: mod_w fp32 -> fp16 ---- */
__global__ void __launch_bounds__(256) prep_b_kernel(const float* __restrict__ mod_w) {
    int i = blockIdx.x * 256 + threadIdx.x;
    float4 v = __ldg(((const float4*)mod_w) + i);
    uint2 o;
    o.x = packh2(v.x, v.y);
    o.y = packh2(v.z, v.w);
    ((uint2*)g_Bh)[i] = o;
}

/* ---- gen A: thread owns fixed 16-wide k-slice, 32 rows/block ---- */
__global__ void __launch_bounds__(256) gen_a_kernel(
    const float* __restrict__ x, const float* __restrict__ enc_beta)
{
    int tid = threadIdx.x;
    int k0 = tid * 16;
    int c  = tid >> 5;

    float4 w0 = *(const float4*)&g_wg[k0],   w1 = *(const float4*)&g_wg[k0+4];
    float4 w2 = *(const float4*)&g_wg[k0+8], w3 = *(const float4*)&g_wg[k0+12];
    float4 b0 = *(const float4*)&g_bg[k0],   b1 = *(const float4*)&g_bg[k0+4];
    float4 b2 = *(const float4*)&g_bg[k0+8], b3 = *(const float4*)&g_bg[k0+12];
    float4 t0 = __ldg((const float4*)&enc_beta[k0]);
    float4 t1 = __ldg((const float4*)&enc_beta[k0+4]);
    float4 t2 = __ldg((const float4*)&enc_beta[k0+8]);
    float4 t3 = __ldg((const float4*)&enc_beta[k0+12]);
    float qa = g_q[c*4+0], qb = g_q[c*4+1], qc = g_q[c*4+2];

    int row0 = blockIdx.x * 32;
    for (int ri = 0; ri < 32; ri++) {
        int token = row0 + ri;
        float xv = __ldg(&x[c*TTOK + token]);
        float rr = rsqrtf(fmaf(xv, fmaf(xv, qa, qb), qc) + EPS_F);
        uint4 o0, o1;
        #define G(W,B,T) gelu_fast(fmaf(fmaf(xv,(W),(B)), rr, (T)))
        o0.x = packh2(G(w0.x,b0.x,t0.x), G(w0.y,b0.y,t0.y));
        o0.y = packh2(G(w0.z,b0.z,t0.z), G(w0.w,b0.w,t0.w));
        o0.z = packh2(G(w1.x,b1.x,t1.x), G(w1.y,b1.y,t1.y));
        o0.w = packh2(G(w1.z,b1.z,t1.z), G(w1.w,b1.w,t1.w));
        o1.x = packh2(G(w2.x,b2.x,t2.x), G(w2.y,b2.y,t2.y));
        o1.y = packh2(G(w2.z,b2.z,t2.z), G(w2.w,b2.w,t2.w));
        o1.z = packh2(G(w3.x,b3.x,t3.x), G(w3.y,b3.y,t3.y));
        o1.w = packh2(G(w3.z,b3.z,t3.z), G(w3.w,b3.w,t3.w));
        #undef G
        uint4* dst = (uint4*)(g_Ah + (size_t)token*KTOT + k0);
        dst[0] = o0;
        dst[1] = o1;
    }
}

/* ---- fp16 mma.sync GEMM: 2 independent 128-thread groups per CTA ---- */
__global__ void __launch_bounds__(256, 2) gemm_kernel(float* __restrict__ out)
{
    extern __shared__ char smem[];
    uint32_t sb = smem_u32(smem);
    int tid = threadIdx.x;
    int mt = blockIdx.x >> 1, nt = blockIdx.x & 1;

    int grp  = tid >> 7;          /* 0/1 — independent pipeline */
    int gtid = tid & 127;
    int gwid = gtid >> 5, lane = tid & 31;
    int wr = gwid >> 1, wc = gwid & 1;   /* 2x2 warps over 64x128 */
    int barid = 1 + grp;

    uint32_t gbase = sb + (uint32_t)grp * GRP;

    /* ldmatrix thread offsets with 64B-row XOR swizzle (chunk ^= (row>>1)&3) */
    int rowA = wr*32 + (lane & 15);
    int swzA = ((lane & 15) >> 1) & 3;
    uint32_t aAddr0 = (uint32_t)(rowA*64 + (((lane >> 4)     ^ swzA) * 16));
    uint32_t aAddr1 = (uint32_t)(rowA*64 + (((2 + (lane >> 4)) ^ swzA) * 16));
    int rowB = wc*64 + ((lane >> 4) & 1)*8 + (lane & 7);
    int swzB = ((((lane >> 4) & 1)*8 + (lane & 7)) >> 1) & 3;
    uint32_t bAddr0 = (uint32_t)(rowB*64 + ((((lane >> 3) & 1)     ^ swzB) * 16));
    uint32_t bAddr1 = (uint32_t)(rowB*64 + (((2 + ((lane >> 3) & 1)) ^ swzB) * 16));

    /* cp.async per-thread dst offsets (swizzled) and src pointers */
    int rw0 = gtid >> 2, ch0 = gtid & 3;
    int swzC = (rw0 >> 1) & 3;
    uint32_t cOff0 = (uint32_t)( rw0      *64 + ((ch0 ^ swzC) * 16));
    uint32_t cOff1 = (uint32_t)((rw0+32)  *64 + ((ch0 ^ swzC) * 16));
    uint32_t cOff2 = (uint32_t)((rw0+64)  *64 + ((ch0 ^ swzC) * 16));
    uint32_t cOff3 = (uint32_t)((rw0+96)  *64 + ((ch0 ^ swzC) * 16));

    const __half* Abase = g_Ah + (size_t)(mt*BM)*KTOT;
    const __half* Bbase = g_Bh + (size_t)(nt*256 + grp*128)*KTOT;
    const __half* pA0 = Abase + (size_t)rw0*KTOT + ch0*8;
    const __half* pA1 = Abase + (size_t)(rw0+32)*KTOT + ch0*8;
    const __half* pB0 = Bbase + (size_t)rw0*KTOT + ch0*8;
    const __half* pB1 = Bbase + (size_t)(rw0+32)*KTOT + ch0*8;
    const __half* pB2 = Bbase + (size_t)(rw0+64)*KTOT + ch0*8;
    const __half* pB3 = Bbase + (size_t)(rw0+96)*KTOT + ch0*8;

    float acc[2][8][4];
    #pragma unroll
    for (int mi = 0; mi < 2; mi++)
        #pragma unroll
        for (int ni = 0; ni < 8; ni++)
            #pragma unroll
            for (int e = 0; e < 4; e++) acc[mi][ni][e] = 0.f;

    uint32_t af[2][2][4];
    uint32_t bf[2][8][2];

#define CPA(dst, src)                                                         \
    asm volatile("cp.async.cg.shared.global [%0], [%1], 16;"                  \
                 :: "r"(dst), "l"(src) : "memory")

#define CP_STAGE(sidx, buf)                                                   \
    {                                                                         \
        uint32_t ab = gbase + (buf)*SLAB;                                     \
        uint32_t bb = ab + A_BYTES;                                           \
        CPA(ab + cOff0, pA0 + (sidx)*32);                                     \
        CPA(ab + cOff1, pA1 + (sidx)*32);                                     \
        CPA(bb + cOff0, pB0 + (sidx)*32);                                     \
        CPA(bb + cOff1, pB1 + (sidx)*32);                                     \
        CPA(bb + cOff2, pB2 + (sidx)*32);                                     \
        CPA(bb + cOff3, pB3 + (sidx)*32);                                     \
    }

#define LOAD_FRAGS(buf, kh, ph)                                               \
    {                                                                         \
        uint32_t ab = gbase + (buf)*SLAB + ((kh) ? aAddr1 : aAddr0);          \
        uint32_t bb = gbase + (buf)*SLAB + A_BYTES + ((kh) ? bAddr1 : bAddr0);\
        _Pragma("unroll")                                                     \
        for (int mi = 0; mi < 2; mi++)                                        \
            LDSM4(af[ph][mi][0], af[ph][mi][1], af[ph][mi][2], af[ph][mi][3], \
                  ab + (uint32_t)(mi*1024));                                  \
        _Pragma("unroll")                                                     \
        for (int p = 0; p < 4; p++)                                           \
            LDSM4(bf[ph][2*p][0], bf[ph][2*p][1],                             \
                  bf[ph][2*p+1][0], bf[ph][2*p+1][1],                         \
                  bb + (uint32_t)(p*1024));                                   \
    }

#define MMA_BLOCK(ph)                                                         \
    {                                                                         \
        _Pragma("unroll")                                                     \
        for (int mi = 0; mi < 2; mi++)                                        \
            _Pragma("unroll")                                                 \
            for (int ni = 0; ni < 8; ni++)                                    \
                MMA16816(acc[mi][ni], af[ph][mi], bf[ph][ni]);                \
    }

#define GBAR() asm volatile("bar.sync %0, %1;" :: "r"(barid), "r"(128) : "memory")
#define CPCOMMIT() asm volatile("cp.async.commit_group;" ::: "memory")
#define CPWAIT1() asm volatile("cp.async.wait_group 1;" ::: "memory")

    /* R9-equivalent pipeline, per group.  Stage s: buf s&3.
       wait_group 1 at top of body s (s>0) -> stages <= s+1 resident. */
#define STAGE_BODY(s, fb, nb, pb)                                             \
    {                                                                         \
        if ((s) > 0) { CPWAIT1(); GBAR(); }                                   \
        if ((s) + 3 < NSTG) CP_STAGE((s) + 3, (pb));                          \
        CPCOMMIT();                                                           \
        LOAD_FRAGS((fb), 1, 1);                                               \
        MMA_BLOCK(0);                                                         \
        if ((s) + 1 < NSTG) LOAD_FRAGS((nb), 0, 0);                           \
        MMA_BLOCK(1);                                                         \
    }

    /* prologue: 3 stages in flight */
    CP_STAGE(0, 0); CPCOMMIT();
    CP_STAGE(1, 1); CPCOMMIT();
    CP_STAGE(2, 2); CPCOMMIT();
    CPWAIT1();
    GBAR();
    LOAD_FRAGS(0, 0, 0);

    for (int s4 = 0; s4 < NSTG; s4 += 4) {
        { int s = s4 + 0; STAGE_BODY(s, 0, 1, 3); }
        { int s = s4 + 1; STAGE_BODY(s, 1, 2, 0); }
        { int s = s4 + 2; STAGE_BODY(s, 2, 3, 1); }
        { int s = s4 + 3; STAGE_BODY(s, 3, 0, 2); }
    }

    /* epilogue: raw y (pre-bias) to gmem; groups own distinct columns */
    int gr = mt*BM + wr*32;
    int gc = nt*256 + grp*128 + wc*64;
    #pragma unroll
    for (int mi = 0; mi < 2; mi++) {
        int row0 = gr + mi*16 + (lane >> 2);
        #pragma unroll
        for (int ni = 0; ni < 8; ni++) {
            int col = gc + ni*8 + ((lane & 3) << 1);
            *(float2*)&out[(size_t)row0*HDIM + col] =
                make_float2(acc[mi][ni][0], acc[mi][ni][1]);
            *(float2*)&out[(size_t)(row0+8)*HDIM + col] =
                make_float2(acc[mi][ni][2], acc[mi][ni][3]);
        }
    }
}

/* ---- bias + LayerNorm + GELU (exact erff), row-per-block ---- */
__global__ void __launch_bounds__(128) ln_gelu_kernel(
    float* __restrict__ y, const float* __restrict__ mod_b,
    const float* __restrict__ mg, const float* __restrict__ mb)
{
    __shared__ float red[8];
    int t = threadIdx.x, lane = t & 31, w = t >> 5;
    size_t base = (size_t)blockIdx.x * HDIM;
    float4 v = *(float4*)&y[base + t*4];
    float4 b = __ldg((const float4*)&mod_b[t*4]);
    v.x += b.x; v.y += b.y; v.z += b.z; v.w += b.w;
    float s = v.x + v.y + v.z + v.w;
    float q = v.x*v.x + v.y*v.y + v.z*v.z + v.w*v.w;
    #pragma unroll
    for (int o = 16; o > 0; o >>= 1) {
        s += __shfl_xor_sync(0xffffffffu, s, o);
        q += __shfl_xor_sync(0xffffffffu, q, o);
    }
    if (lane == 0) { red[w] = s; red[4+w] = q; }
    __syncthreads();
    float S = red[0]+red[1]+red[2]+red[3];
    float Q = red[4]+red[5]+red[6]+red[7];
    float mu = S * (1.0f/HDIM);
    float var = Q * (1.0f/HDIM) - mu*mu;
    float rrv = rsqrtf(var + EPS_F);
    float4 g = __ldg((const float4*)&mg[t*4]);
    float4 be = __ldg((const float4*)&mb[t*4]);
    float4 o;
    o.x = geluf(fmaf((v.x-mu)*rrv, g.x, be.x));
    o.y = geluf(fmaf((v.y-mu)*rrv, g.y, be.y));
    o.z = geluf(fmaf((v.z-mu)*rrv, g.z, be.z));
    o.w = geluf(fmaf((v.w-mu)*rrv, g.w, be.w));
    *(float4*)&y[base + t*4] = o;
}

extern "C" void kernel_launch(void* const* d_in, const int* in_sizes, int n_in,
                              void* d_out, int out_size) {
    const float* x         = (const float*)d_in[0];
    const float* enc_w     = (const float*)d_in[1];
    const float* enc_b     = (const float*)d_in[2];
    const float* enc_gamma = (const float*)d_in[3];
    const float* enc_beta  = (const float*)d_in[4];
    const float* mod_w     = (const float*)d_in[5];
    const float* mod_b     = (const float*)d_in[6];
    const float* mod_gamma = (const float*)d_in[7];
    const float* mod_beta  = (const float*)d_in[8];
    float* out = (float*)d_out;

    cudaFuncSetAttribute(gemm_kernel,
                         cudaFuncAttributeMaxDynamicSharedMemorySize, SMEM_TOTAL);

    prep_channel_kernel<<<NCH, 512>>>(enc_w, enc_b, enc_gamma);
    prep_b_kernel<<<(HDIM*KTOT/4)/256, 256>>>(mod_w);
    gen_a_kernel<<<TTOK/32, 256>>>(x, enc_beta);
    gemm_kernel<<<(TTOK/BM)*2, 256, SMEM_TOTAL>>>(out);
    ln_gelu_kernel<<<TTOK, 128>>>(out, mod_b, mod_gamma, mod_beta);
}

// round 16
// speedup vs baseline: 2.0357x; 1.1153x over previous
#include <cuda_runtime.h>
#include <cuda_fp16.h>
#include <cstdint>

#define NCH   8
#define HDIM  512
#define TTOK  32768
#define KTOT  4096
#define BM    64
#define BK    64
#define NSTG  (KTOT/BK)      /* 64 */
#define EPS_F 1e-5f

/* per-group stage slab: A 64x128B (8192) + B 128x128B (16384) = 24576; 2-ring x 2 groups */
#define A_BYTES  8192
#define SLAB     24576
#define GRP      (2*SLAB)             /* 49152 */
#define SMEM_TOTAL (2*GRP)            /* 98304 */

__device__ float  g_wg[NCH*HDIM];
__device__ float  g_bg[NCH*HDIM];
__device__ float  g_q[NCH*4];
__device__ __half g_Bh[HDIM*KTOT];
__device__ __half g_Ah[(size_t)TTOK*KTOT];

__device__ __forceinline__ uint32_t smem_u32(const void* p) {
    uint32_t a;
    asm("{ .reg .u64 t; cvta.to.shared.u64 t, %1; cvt.u32.u64 %0, t; }" : "=r"(a) : "l"(p));
    return a;
}
__device__ __forceinline__ float geluf(float v) {
    return 0.5f * v * (1.0f + erff(v * 0.7071067811865476f));
}
__device__ __forceinline__ float gelu_fast(float v) {
    float t = v * v;
    float y = v * fmaf(t, 0.0356774081f, 0.7978845608f);
    float e = __expf(-2.0f * y);
    return __fdividef(v, 1.0f + e);
}
__device__ __forceinline__ uint32_t packh2(float a, float b) {
    __half2 h = __floats2half2_rn(a, b);
    return *reinterpret_cast<uint32_t*>(&h);
}

#define LDSM4(d0, d1, d2, d3, addr)                                           \
    asm volatile("ldmatrix.sync.aligned.m8n8.x4.shared.b16 {%0,%1,%2,%3}, [%4];" \
                 : "=r"(d0), "=r"(d1), "=r"(d2), "=r"(d3) : "r"(addr))
#define MMA16816(c, a, b)                                                     \
    asm volatile("mma.sync.aligned.m16n8k16.row.col.f32.f16.f16.f32 "         \
                 "{%0,%1,%2,%3}, {%4,%5,%6,%7}, {%8,%9}, {%0,%1,%2,%3};"      \
                 : "+f"((c)[0]), "+f"((c)[1]), "+f"((c)[2]), "+f"((c)[3])     \
                 : "r"((a)[0]), "r"((a)[1]), "r"((a)[2]), "r"((a)[3]),        \
                   "r"((b)[0]), "r"((b)[1]))

/* ---- prep 1: per-channel LN closed-form tables ---- */
__device__ __forceinline__ float bsum512(float v, float* red) {
    #pragma unroll
    for (int o = 16; o > 0; o >>= 1) v += __shfl_xor_sync(0xffffffffu, v, o);
    __syncthreads();
    if ((threadIdx.x & 31) == 0) red[threadIdx.x >> 5] = v;
    __syncthreads();
    float s = 0.f;
    #pragma unroll
    for (int i = 0; i < 16; i++) s += red[i];
    return s;
}
__global__ void __launch_bounds__(512) prep_channel_kernel(
    const float* __restrict__ enc_w, const float* __restrict__ enc_b,
    const float* __restrict__ enc_gamma)
{
    __shared__ float red[16];
    int c = blockIdx.x, t = threadIdx.x;
    float w = enc_w[c*HDIM+t], b = enc_b[c*HDIM+t];
    float wm = bsum512(w, red) * (1.0f/HDIM);
    float bm = bsum512(b, red) * (1.0f/HDIM);
    float wp = w - wm, bp = b - bm;
    float sww = bsum512(wp*wp, red);
    float swb = bsum512(wp*bp, red);
    float sbb = bsum512(bp*bp, red);
    float ga = enc_gamma[c*HDIM+t];
    g_wg[c*HDIM+t] = wp * ga;
    g_bg[c*HDIM+t] = bp * ga;
    if (t == 0) {
        g_q[c*4+0] = sww * (1.0f/HDIM);
        g_q[c*4+1] = 2.0f * swb * (1.0f/HDIM);
        g_q[c*4+2] = sbb * (1.0f/HDIM);
    }
}

/* ---- prep 2: mod_w fp32 -> fp16 ---- */
__global__ void __launch_bounds__(256) prep_b_kernel(const float* __restrict__ mod_w) {
    int i = blockIdx.x * 256 + threadIdx.x;
    float4 v = __ldg(((const float4*)mod_w) + i);
    uint2 o;
    o.x = packh2(v.x, v.y);
    o.y = packh2(v.z, v.w);
    ((uint2*)g_Bh)[i] = o;
}

/* ---- gen A: thread owns fixed 16-wide k-slice, 32 rows/block ---- */
__global__ void __launch_bounds__(256) gen_a_kernel(
    const float* __restrict__ x, const float* __restrict__ enc_beta)
{
    int tid = threadIdx.x;
    int k0 = tid * 16;
    int c  = tid >> 5;

    float4 w0 = *(const float4*)&g_wg[k0],   w1 = *(const float4*)&g_wg[k0+4];
    float4 w2 = *(const float4*)&g_wg[k0+8], w3 = *(const float4*)&g_wg[k0+12];
    float4 b0 = *(const float4*)&g_bg[k0],   b1 = *(const float4*)&g_bg[k0+4];
    float4 b2 = *(const float4*)&g_bg[k0+8], b3 = *(const float4*)&g_bg[k0+12];
    float4 t0 = __ldg((const float4*)&enc_beta[k0]);
    float4 t1 = __ldg((const float4*)&enc_beta[k0+4]);
    float4 t2 = __ldg((const float4*)&enc_beta[k0+8]);
    float4 t3 = __ldg((const float4*)&enc_beta[k0+12]);
    float qa = g_q[c*4+0], qb = g_q[c*4+1], qc = g_q[c*4+2];

    int row0 = blockIdx.x * 32;
    for (int ri = 0; ri < 32; ri++) {
        int token = row0 + ri;
        float xv = __ldg(&x[c*TTOK + token]);
        float rr = rsqrtf(fmaf(xv, fmaf(xv, qa, qb), qc) + EPS_F);
        uint4 o0, o1;
        #define G(W,B,T) gelu_fast(fmaf(fmaf(xv,(W),(B)), rr, (T)))
        o0.x = packh2(G(w0.x,b0.x,t0.x), G(w0.y,b0.y,t0.y));
        o0.y = packh2(G(w0.z,b0.z,t0.z), G(w0.w,b0.w,t0.w));
        o0.z = packh2(G(w1.x,b1.x,t1.x), G(w1.y,b1.y,t1.y));
        o0.w = packh2(G(w1.z,b1.z,t1.z), G(w1.w,b1.w,t1.w));
        o1.x = packh2(G(w2.x,b2.x,t2.x), G(w2.y,b2.y,t2.y));
        o1.y = packh2(G(w2.z,b2.z,t2.z), G(w2.w,b2.w,t2.w));
        o1.z = packh2(G(w3.x,b3.x,t3.x), G(w3.y,b3.y,t3.y));
        o1.w = packh2(G(w3.z,b3.z,t3.z), G(w3.w,b3.w,t3.w));
        #undef G
        uint4* dst = (uint4*)(g_Ah + (size_t)token*KTOT + k0);
        dst[0] = o0;
        dst[1] = o1;
    }
}

/* ---- fp16 mma.sync GEMM: 2 independent groups, BK=64, 2-buf ring ---- */
__global__ void __launch_bounds__(256, 2) gemm_kernel(float* __restrict__ out)
{
    extern __shared__ char smem[];
    uint32_t sb = smem_u32(smem);
    int tid = threadIdx.x;
    int mt = blockIdx.x >> 1, nt = blockIdx.x & 1;

    int grp  = tid >> 7;
    int gtid = tid & 127;
    int gwid = gtid >> 5, lane = tid & 31;
    int wr = gwid >> 1, wc = gwid & 1;   /* 2x2 warps over 64x128 */
    int barid = 1 + grp;

    uint32_t gbase = sb + (uint32_t)grp * GRP;

    /* ldmatrix bases: 128B rows, swizzle chunk ^= (row & 7); swz invariant
       under +16-row steps used by mi / p offsets. */
    int rowA = wr*32 + (lane & 15);
    int swzA = rowA & 7;
    int selA = lane >> 4;                /* 0/1 */
    uint32_t aRowBase = (uint32_t)(rowA * 128);
    int rowB = wc*64 + ((lane >> 4) & 1)*8 + (lane & 7);
    int swzB = rowB & 7;
    int selB = (lane >> 3) & 1;
    uint32_t bRowBase = (uint32_t)(rowB * 128);

    /* cp.async: 128 threads; A 512x16B units (4/thr), B 1024 (8/thr) */
    int rw0 = gtid >> 3, ch0 = gtid & 7;
    uint32_t cDstA = (uint32_t)(rw0*128 + ((ch0 ^ (rw0 & 7)) * 16));
    /* +16 rows per i keeps (row&7) fixed -> dst step = 16*128 = 2048 */

    const __half* Abase = g_Ah + (size_t)(mt*BM)*KTOT;
    const __half* Bbase = g_Bh + (size_t)(nt*256 + grp*128)*KTOT;
    const __half* pA0 = Abase + (size_t)rw0*KTOT + ch0*8;
    const __half* pB0 = Bbase + (size_t)rw0*KTOT + ch0*8;

    float acc[2][8][4];
    #pragma unroll
    for (int mi = 0; mi < 2; mi++)
        #pragma unroll
        for (int ni = 0; ni < 8; ni++)
            #pragma unroll
            for (int e = 0; e < 4; e++) acc[mi][ni][e] = 0.f;

    uint32_t af[2][2][4];
    uint32_t bf[2][8][2];

#define CPA(dst, src)                                                         \
    asm volatile("cp.async.cg.shared.global [%0], [%1], 16;"                  \
                 :: "r"(dst), "l"(src) : "memory")

#define CP_STAGE(sidx, buf)                                                   \
    {                                                                         \
        uint32_t ab = gbase + (buf)*SLAB;                                     \
        uint32_t bb = ab + A_BYTES;                                           \
        _Pragma("unroll")                                                     \
        for (int i = 0; i < 4; i++)                                           \
            CPA(ab + cDstA + (uint32_t)(i*2048),                              \
                pA0 + (size_t)i*16*KTOT + (sidx)*64);                         \
        _Pragma("unroll")                                                     \
        for (int i = 0; i < 8; i++)                                           \
            CPA(bb + cDstA + (uint32_t)(i*2048),                              \
                pB0 + (size_t)i*16*KTOT + (sidx)*64);                         \
    }

/* kh in 0..3 selects 32B k-slice: chunks {2kh, 2kh+1} */
#define LOAD_FRAGS(buf, kh, ph)                                               \
    {                                                                         \
        uint32_t aa = gbase + (buf)*SLAB + aRowBase                           \
                      + (uint32_t)((((2*(kh) + selA) ^ swzA)) * 16);          \
        uint32_t bb2 = gbase + (buf)*SLAB + A_BYTES + bRowBase                \
                      + (uint32_t)((((2*(kh) + selB) ^ swzB)) * 16);          \
        _Pragma("unroll")                                                     \
        for (int mi = 0; mi < 2; mi++)                                        \
            LDSM4(af[ph][mi][0], af[ph][mi][1], af[ph][mi][2], af[ph][mi][3], \
                  aa + (uint32_t)(mi*2048));                                  \
        _Pragma("unroll")                                                     \
        for (int p = 0; p < 4; p++)                                           \
            LDSM4(bf[ph][2*p][0], bf[ph][2*p][1],                             \
                  bf[ph][2*p+1][0], bf[ph][2*p+1][1],                         \
                  bb2 + (uint32_t)(p*2048));                                  \
    }

#define MMA_BLOCK(ph)                                                         \
    {                                                                         \
        _Pragma("unroll")                                                     \
        for (int mi = 0; mi < 2; mi++)                                        \
            _Pragma("unroll")                                                 \
            for (int ni = 0; ni < 8; ni++)                                    \
                MMA16816(acc[mi][ni], af[ph][mi], bf[ph][ni]);                \
    }

#define GBAR() asm volatile("bar.sync %0, %1;" :: "r"(barid), "r"(128) : "memory")
#define CPCOMMIT() asm volatile("cp.async.commit_group;" ::: "memory")
#define CPWAIT1() asm volatile("cp.async.wait_group 1;" ::: "memory")
#define CPWAIT0() asm volatile("cp.async.wait_group 0;" ::: "memory")

    /* Stage s uses buf b = s&1.  Visibility invariant (per-thread cp.async
       tracking): every smem read of stage t data happens after
       [every thread: wait for own stage-t group] -> group barrier.
       Body: compute kh0..2 (kh0 preloaded), then WAIT0+GBAR (stage s+1 now
       visible to ALL; also all reads of buf b are done), CP stage s+2 into
       buf b, prefetch stage s+1 kh0, compute kh3. */
#define STAGE_BODY(s, b)                                                      \
    {                                                                         \
        LOAD_FRAGS(b, 1, 1);  MMA_BLOCK(0);                                   \
        LOAD_FRAGS(b, 2, 0);  MMA_BLOCK(1);                                   \
        LOAD_FRAGS(b, 3, 1);  MMA_BLOCK(0);                                   \
        if ((s) + 1 < NSTG) { CPWAIT0(); GBAR(); }                            \
        if ((s) + 2 < NSTG) { CP_STAGE((s) + 2, b); CPCOMMIT(); }             \
        if ((s) + 1 < NSTG) LOAD_FRAGS(b ^ 1, 0, 0);                          \
        MMA_BLOCK(1);                                                         \
    }

    /* prologue: 2 stages in flight; stage 0 visible after WAIT1+GBAR */
    CP_STAGE(0, 0); CPCOMMIT();
    CP_STAGE(1, 1); CPCOMMIT();
    CPWAIT1();
    GBAR();
    LOAD_FRAGS(0, 0, 0);

    for (int s2 = 0; s2 < NSTG; s2 += 2) {
        { int s = s2 + 0; STAGE_BODY(s, 0); }
        { int s = s2 + 1; STAGE_BODY(s, 1); }
    }

    /* epilogue: raw y (pre-bias) to gmem; groups own distinct columns */
    int gr = mt*BM + wr*32;
    int gc = nt*256 + grp*128 + wc*64;
    #pragma unroll
    for (int mi = 0; mi < 2; mi++) {
        int row0 = gr + mi*16 + (lane >> 2);
        #pragma unroll
        for (int ni = 0; ni < 8; ni++) {
            int col = gc + ni*8 + ((lane & 3) << 1);
            *(float2*)&out[(size_t)row0*HDIM + col] =
                make_float2(acc[mi][ni][0], acc[mi][ni][1]);
            *(float2*)&out[(size_t)(row0+8)*HDIM + col] =
                make_float2(acc[mi][ni][2], acc[mi][ni][3]);
        }
    }
}

/* ---- bias + LayerNorm + GELU (exact erff), row-per-block ---- */
__global__ void __launch_bounds__(128) ln_gelu_kernel(
    float* __restrict__ y, const float* __restrict__ mod_b,
    const float* __restrict__ mg, const float* __restrict__ mb)
{
    __shared__ float red[8];
    int t = threadIdx.x, lane = t & 31, w = t >> 5;
    size_t base = (size_t)blockIdx.x * HDIM;
    float4 v = *(float4*)&y[base + t*4];
    float4 b = __ldg((const float4*)&mod_b[t*4]);
    v.x += b.x; v.y += b.y; v.z += b.z; v.w += b.w;
    float s = v.x + v.y + v.z + v.w;
    float q = v.x*v.x + v.y*v.y + v.z*v.z + v.w*v.w;
    #pragma unroll
    for (int o = 16; o > 0; o >>= 1) {
        s += __shfl_xor_sync(0xffffffffu, s, o);
        q += __shfl_xor_sync(0xffffffffu, q, o);
    }
    if (lane == 0) { red[w] = s; red[4+w] = q; }
    __syncthreads();
    float S = red[0]+red[1]+red[2]+red[3];
    float Q = red[4]+red[5]+red[6]+red[7];
    float mu = S * (1.0f/HDIM);
    float var = Q * (1.0f/HDIM) - mu*mu;
    float rrv = rsqrtf(var + EPS_F);
    float4 g = __ldg((const float4*)&mg[t*4]);
    float4 be = __ldg((const float4*)&mb[t*4]);
    float4 o;
    o.x = geluf(fmaf((v.x-mu)*rrv, g.x, be.x));
    o.y = geluf(fmaf((v.y-mu)*rrv, g.y, be.y));
    o.z = geluf(fmaf((v.z-mu)*rrv, g.z, be.z));
    o.w = geluf(fmaf((v.w-mu)*rrv, g.w, be.w));
    *(float4*)&y[base + t*4] = o;
}

extern "C" void kernel_launch(void* const* d_in, const int* in_sizes, int n_in,
                              void* d_out, int out_size) {
    const float* x         = (const float*)d_in[0];
    const float* enc_w     = (const float*)d_in[1];
    const float* enc_b     = (const float*)d_in[2];
    const float* enc_gamma = (const float*)d_in[3];
    const float* enc_beta  = (const float*)d_in[4];
    const float* mod_w     = (const float*)d_in[5];
    const float* mod_b     = (const float*)d_in[6];
    const float* mod_gamma = (const float*)d_in[7];
    const float* mod_beta  = (const float*)d_in[8];
    float* out = (float*)d_out;

    cudaFuncSetAttribute(gemm_kernel,
                         cudaFuncAttributeMaxDynamicSharedMemorySize, SMEM_TOTAL);

    prep_channel_kernel<<<NCH, 512>>>(enc_w, enc_b, enc_gamma);
    prep_b_kernel<<<(HDIM*KTOT/4)/256, 256>>>(mod_w);
    gen_a_kernel<<<TTOK/32, 256>>>(x, enc_beta);
    gemm_kernel<<<(TTOK/BM)*2, 256, SMEM_TOTAL>>>(out);
    ln_gelu_kernel<<<TTOK, 128>>>(out, mod_b, mod_gamma, mod_beta);
}